// round 4
// baseline (speedup 1.0000x reference)
#include <cuda_runtime.h>
#include <cstdint>
#include <cstddef>

#define NN   100000
#define EE   1600000
#define DIN  165
#define DMID 82
#define DH   128
#define DG   64

typedef unsigned long long ull;

// ---------------- scratch (static device globals) ---------------------------
__device__ float g_t  [NN * DMID];   // relu(x@W1)
__device__ float g_y1 [NN * DIN];    // boosted features
__device__ float g_zl [NN * DH];     // y1 @ sage_wl
__device__ float g_zr [NN * DH];     // y1 @ sage_wr
__device__ float g_x2 [NN * DH];     // SAGE output
__device__ float g_h  [NN * DG];     // GAT projected features
__device__ float g_as [NN];
__device__ float g_ad [NN];
__device__ int   g_cnt [NN];
__device__ int   g_rowptr[NN + 1];
__device__ int   g_cursor[NN];
__device__ int   g_bsum[256];
__device__ int   g_col [EE];

// ---------------- helpers ----------------------------------------------------
__device__ __forceinline__ float wredmax(float v) {
    #pragma unroll
    for (int o = 16; o; o >>= 1) v = fmaxf(v, __shfl_xor_sync(0xffffffffu, v, o));
    return v;
}
__device__ __forceinline__ float wredsum(float v) {
    #pragma unroll
    for (int o = 16; o; o >>= 1) v += __shfl_xor_sync(0xffffffffu, v, o);
    return v;
}
#define FMA2(acc, a, b) asm("fma.rn.f32x2 %0, %1, %2, %0;" : "+l"(acc) : "l"(a), "l"(b))
#define UNPK(p, lo, hi) asm("mov.b64 {%0,%1}, %2;" : "=f"(lo), "=f"(hi) : "l"(p))

// ---------------- CSR build --------------------------------------------------
__global__ void k_zero_cnt(int n) {
    int i = blockIdx.x * blockDim.x + threadIdx.x;
    if (i < n) g_cnt[i] = 0;
}

__global__ void k_hist(const int* __restrict__ ei, int e, int n) {
    int i = blockIdx.x * blockDim.x + threadIdx.x;
    if (i < e) {
        int d = ei[e + i];
        if ((unsigned)d < (unsigned)n) atomicAdd(&g_cnt[d], 1);
    }
}

__global__ void k_scan1(int n) {
    __shared__ int sh[1024];
    int t = threadIdx.x;
    int i = blockIdx.x * 1024 + t;
    int v = (i < n) ? g_cnt[i] : 0;
    sh[t] = v;
    __syncthreads();
    #pragma unroll
    for (int off = 1; off < 1024; off <<= 1) {
        int x = (t >= off) ? sh[t - off] : 0;
        __syncthreads();
        sh[t] += x;
        __syncthreads();
    }
    int incl = sh[t];
    if (i < n) g_rowptr[i] = incl - v;
    if (t == 1023) g_bsum[blockIdx.x] = incl;
}

__global__ void k_scan2(int nb) {
    __shared__ int sh[256];
    int t = threadIdx.x;
    int v = (t < nb) ? g_bsum[t] : 0;
    sh[t] = v;
    __syncthreads();
    #pragma unroll
    for (int off = 1; off < 256; off <<= 1) {
        int x = (t >= off) ? sh[t - off] : 0;
        __syncthreads();
        sh[t] += x;
        __syncthreads();
    }
    if (t < nb) g_bsum[t] = sh[t] - v;   // exclusive
}

__global__ void k_scan3(int n, int e) {
    int i = blockIdx.x * blockDim.x + threadIdx.x;
    if (i < n) {
        int v = g_rowptr[i] + g_bsum[i >> 10];
        g_rowptr[i] = v;
        g_cursor[i] = v;
    }
    if (i == 0) g_rowptr[n] = e;
}

__global__ void k_fill(const int* __restrict__ ei, int e, int n) {
    int i = blockIdx.x * blockDim.x + threadIdx.x;
    if (i < e) {
        int d = ei[e + i];
        int s = ei[i];
        if ((unsigned)d < (unsigned)n && (unsigned)s < (unsigned)n) {
            int pos = atomicAdd(&g_cursor[d], 1);
            g_col[pos] = s;
        }
    }
}

// ---------------- packed-FFMA2 SGEMM core (64x64 tile, 4x4 microtile) -------
// A stored DUPLICATED as float2 (a,a); W loaded as ulonglong2 -> two f32x2 pairs.
template<int K, typename WF>
__device__ __forceinline__ void gemm_tile_p(
    const float* __restrict__ A, int n, int rowBase, int tid, WF wfetch,
    ull (&acc)[4][2], float2 (*sA)[33], float (*sW)[64])
{
    const int tx = tid & 15, ty = tid >> 4;
    for (int k0 = 0; k0 < K; k0 += 32) {
        #pragma unroll
        for (int i = 0; i < 8; i++) {
            int idx = tid + i * 256;
            int r = idx >> 5, kk = idx & 31;
            int row = rowBase + r, k = k0 + kk;
            float v = (row < n && k < K) ? A[(size_t)row * K + k] : 0.0f;
            sA[r][kk] = make_float2(v, v);
        }
        #pragma unroll
        for (int i = 0; i < 8; i++) {
            int idx = tid + i * 256;
            int kk = idx >> 6, c = idx & 63;
            sW[kk][c] = wfetch(k0 + kk, c);
        }
        __syncthreads();
        #pragma unroll
        for (int kk = 0; kk < 32; kk++) {
            ulonglong2 bb = *(const ulonglong2*)&sW[kk][tx * 4];
            #pragma unroll
            for (int i = 0; i < 4; i++) {
                ull a2 = *(const ull*)&sA[ty * 4 + i][kk];
                FMA2(acc[i][0], a2, bb.x);
                FMA2(acc[i][1], a2, bb.y);
            }
        }
        __syncthreads();
    }
}

// FB stage 1: g_t = relu(x @ fb_w1)
__global__ __launch_bounds__(256) void k_fb1(const float* __restrict__ x,
                                             const float* __restrict__ w1, int n)
{
    __shared__ float2 sA[64][33];
    __shared__ float  sW[32][64];
    ull acc[4][2] = {};
    int tid = threadIdx.x;
    int rowBase = blockIdx.y * 64, colBase = blockIdx.x * 64;
    auto wf = [&](int k, int c) -> float {
        int col = colBase + c;
        return (k < DIN && col < DMID) ? w1[(size_t)k * DMID + col] : 0.0f;
    };
    gemm_tile_p<DIN>(x, n, rowBase, tid, wf, acc, sA, sW);
    int tx = tid & 15, ty = tid >> 4;
    #pragma unroll
    for (int i = 0; i < 4; i++) {
        int r = rowBase + ty * 4 + i;
        if (r >= n) continue;
        #pragma unroll
        for (int jp = 0; jp < 2; jp++) {
            float lo, hi; UNPK(acc[i][jp], lo, hi);
            int c = colBase + tx * 4 + jp * 2;
            if (c     < DMID) g_t[(size_t)r * DMID + c]     = fmaxf(lo, 0.0f);
            if (c + 1 < DMID) g_t[(size_t)r * DMID + c + 1] = fmaxf(hi, 0.0f);
        }
    }
}

// FB stage 2: g_y1 = x * sigmoid(2 * (g_t @ fb_w2))
__global__ __launch_bounds__(256) void k_fb2(const float* __restrict__ x,
                                             const float* __restrict__ w2, int n)
{
    __shared__ float2 sA[64][33];
    __shared__ float  sW[32][64];
    ull acc[4][2] = {};
    int tid = threadIdx.x;
    int rowBase = blockIdx.y * 64, colBase = blockIdx.x * 64;
    auto wf = [&](int k, int c) -> float {
        int col = colBase + c;
        return (k < DMID && col < DIN) ? w2[(size_t)k * DIN + col] : 0.0f;
    };
    gemm_tile_p<DMID>(g_t, n, rowBase, tid, wf, acc, sA, sW);
    int tx = tid & 15, ty = tid >> 4;
    #pragma unroll
    for (int i = 0; i < 4; i++) {
        int r = rowBase + ty * 4 + i;
        if (r >= n) continue;
        #pragma unroll
        for (int jp = 0; jp < 2; jp++) {
            float v[2]; UNPK(acc[i][jp], v[0], v[1]);
            #pragma unroll
            for (int u = 0; u < 2; u++) {
                int c = colBase + tx * 4 + jp * 2 + u;
                if (c < DIN) {
                    float sig = 1.0f / (1.0f + __expf(-2.0f * v[u]));
                    g_y1[(size_t)r * DIN + c] = x[(size_t)r * DIN + c] * sig;
                }
            }
        }
    }
}

// SAGE dual GEMM: [zl | zr] = y1 @ [wl | wr]   (M = 256, 4 col tiles)
__global__ __launch_bounds__(256) void k_dual(const float* __restrict__ wl,
                                              const float* __restrict__ wr, int n)
{
    __shared__ float2 sA[64][33];
    __shared__ float  sW[32][64];
    ull acc[4][2] = {};
    int tid = threadIdx.x;
    int rowBase = blockIdx.y * 64, colBase = blockIdx.x * 64;
    auto wf = [&](int k, int c) -> float {
        if (k >= DIN) return 0.0f;
        int col = colBase + c;
        return (col < DH) ? wl[(size_t)k * DH + col] : wr[(size_t)k * DH + (col - DH)];
    };
    gemm_tile_p<DIN>(g_y1, n, rowBase, tid, wf, acc, sA, sW);
    int tx = tid & 15, ty = tid >> 4;
    float* dstBase = (colBase < DH) ? g_zl : g_zr;
    int colOff = (colBase < DH) ? colBase : colBase - DH;
    #pragma unroll
    for (int i = 0; i < 4; i++) {
        int r = rowBase + ty * 4 + i;
        if (r >= n) continue;
        #pragma unroll
        for (int jp = 0; jp < 2; jp++) {
            float lo, hi; UNPK(acc[i][jp], lo, hi);
            int c = colOff + tx * 4 + jp * 2;
            dstBase[(size_t)r * DH + c]     = lo;
            dstBase[(size_t)r * DH + c + 1] = hi;
        }
    }
}

// SAGE finalize: x2 = relu(mean_gather(zl) + zr + bl)   (warp per node)
__global__ __launch_bounds__(256) void k_sage_fin(const float* __restrict__ bl, int n)
{
    int w = (blockIdx.x * blockDim.x + threadIdx.x) >> 5;
    int lane = threadIdx.x & 31;
    if (w >= n) return;
    int beg = g_rowptr[w], end = g_rowptr[w + 1];
    float4 acc = make_float4(0.f, 0.f, 0.f, 0.f);
    int e = beg;
    for (; e + 2 <= end; e += 2) {
        const float4* p0 = (const float4*)(g_zl + (size_t)g_col[e]     * DH);
        const float4* p1 = (const float4*)(g_zl + (size_t)g_col[e + 1] * DH);
        float4 a = p0[lane], b = p1[lane];
        acc.x += a.x + b.x; acc.y += a.y + b.y;
        acc.z += a.z + b.z; acc.w += a.w + b.w;
    }
    if (e < end) {
        const float4* p0 = (const float4*)(g_zl + (size_t)g_col[e] * DH);
        float4 a = p0[lane];
        acc.x += a.x; acc.y += a.y; acc.z += a.z; acc.w += a.w;
    }
    float inv = 1.0f / fmaxf((float)(end - beg), 1.0f);
    const float4* zr = (const float4*)(g_zr + (size_t)w * DH);
    const float4* bl4 = (const float4*)bl;
    float4 z = zr[lane], b4 = bl4[lane];
    float4 o;
    o.x = fmaxf(acc.x * inv + z.x + b4.x, 0.0f);
    o.y = fmaxf(acc.y * inv + z.y + b4.y, 0.0f);
    o.z = fmaxf(acc.z * inv + z.z + b4.z, 0.0f);
    o.w = fmaxf(acc.w * inv + z.w + b4.w, 0.0f);
    ((float4*)(g_x2 + (size_t)w * DH))[lane] = o;
}

// GAT projection + attention logits fused: g_h = x2 @ gat_w; as/ad per row.
__global__ __launch_bounds__(256) void k_gat_h(const float* __restrict__ gw,
                                               const float* __restrict__ att_s,
                                               const float* __restrict__ att_d, int n)
{
    __shared__ float2 sA[64][33];
    __shared__ float  sW[32][64];
    ull acc[4][2] = {};
    int tid = threadIdx.x;
    int rowBase = blockIdx.y * 64;
    auto wf = [&](int k, int c) -> float {
        return (k < DH && c < DG) ? gw[(size_t)k * DG + c] : 0.0f;
    };
    gemm_tile_p<DH>(g_x2, n, rowBase, tid, wf, acc, sA, sW);
    int tx = tid & 15, ty = tid >> 4;
    #pragma unroll
    for (int i = 0; i < 4; i++) {
        int r = rowBase + ty * 4 + i;
        float ps = 0.0f, pd = 0.0f;
        #pragma unroll
        for (int jp = 0; jp < 2; jp++) {
            float v[2]; UNPK(acc[i][jp], v[0], v[1]);
            #pragma unroll
            for (int u = 0; u < 2; u++) {
                int c = tx * 4 + jp * 2 + u;
                if (r < n) g_h[(size_t)r * DG + c] = v[u];
                ps += v[u] * att_s[c];
                pd += v[u] * att_d[c];
            }
        }
        // reduce across the 16 tx lanes of this half-warp
        #pragma unroll
        for (int o = 8; o; o >>= 1) {
            ps += __shfl_xor_sync(0xffffffffu, ps, o);
            pd += __shfl_xor_sync(0xffffffffu, pd, o);
        }
        if (tx == 0 && r < n) { g_as[r] = ps; g_ad[r] = pd; }
    }
}

// GAT softmax-aggregate + bias + relu + Cheb(64->1) + sigmoid, fully fused.
__global__ __launch_bounds__(256) void k_gat_agg(const float* __restrict__ gat_b,
                                                 const float* __restrict__ cheb_w,
                                                 const float* __restrict__ cheb_b,
                                                 float* __restrict__ out, int n)
{
    int w = (blockIdx.x * blockDim.x + threadIdx.x) >> 5;
    int lane = threadIdx.x & 31;
    if (w >= n) return;
    int beg = g_rowptr[w], end = g_rowptr[w + 1];
    float ad_i = g_ad[w];
    float es = g_as[w] + ad_i;
    es = es > 0.0f ? es : 0.2f * es;            // self-loop leaky relu
    float m = es;
    for (int base = beg; base < end; base += 32) {
        int j = base + lane;
        float e = -1e30f;
        if (j < end) {
            int s = g_col[j];
            float t = g_as[s] + ad_i;
            e = t > 0.0f ? t : 0.2f * t;
        }
        m = fmaxf(m, e);
    }
    m = wredmax(m);
    float sl = 0.0f, a0 = 0.0f, a1 = 0.0f;
    for (int base = beg; base < end; base += 32) {
        int j = base + lane;
        int s = 0;
        float wgt = 0.0f;
        if (j < end) {
            s = g_col[j];
            float t = g_as[s] + ad_i;
            t = t > 0.0f ? t : 0.2f * t;
            wgt = __expf(t - m);
        }
        sl += wgt;
        int cnt = min(32, end - base);
        for (int jj = 0; jj < cnt; jj++) {
            float wj = __shfl_sync(0xffffffffu, wgt, jj);
            int   sj = __shfl_sync(0xffffffffu, s, jj);
            float2 hv = ((const float2*)(g_h + (size_t)sj * DG))[lane];
            a0 += wj * hv.x;
            a1 += wj * hv.y;
        }
    }
    float ws = __expf(es - m);
    float stot = wredsum(sl) + ws;
    float2 hi = ((const float2*)(g_h + (size_t)w * DG))[lane];
    a0 += ws * hi.x;
    a1 += ws * hi.y;
    float r = 1.0f / (stot + 1e-16f);
    float x0 = fmaxf(a0 * r + gat_b[2 * lane],     0.0f);
    float x1 = fmaxf(a1 * r + gat_b[2 * lane + 1], 0.0f);
    float part = x0 * cheb_w[2 * lane] + x1 * cheb_w[2 * lane + 1];
    part = wredsum(part);
    if (lane == 0) out[w] = 1.0f / (1.0f + __expf(-(part + cheb_b[0])));
}

// ---------------- launch -----------------------------------------------------
extern "C" void kernel_launch(void* const* d_in, const int* in_sizes, int n_in,
                              void* d_out, int out_size)
{
    const float* x       = (const float*)d_in[0];
    const int*   ei      = (const int*)d_in[1];       // int32
    const float* fb_w1   = (const float*)d_in[2];
    const float* fb_w2   = (const float*)d_in[3];
    const float* sage_wl = (const float*)d_in[4];
    const float* sage_bl = (const float*)d_in[5];
    const float* sage_wr = (const float*)d_in[6];
    const float* gat_w   = (const float*)d_in[7];
    const float* att_s   = (const float*)d_in[8];
    const float* att_d   = (const float*)d_in[9];
    const float* gat_b   = (const float*)d_in[10];
    const float* cheb_w  = (const float*)d_in[11];
    const float* cheb_b  = (const float*)d_in[12];
    float*       out     = (float*)d_out;

    int n = in_sizes[0] / DIN;
    int e = in_sizes[1] / 2;

    // side stream + events for the CSR branch (host objects, created once;
    // the captured graph embeds the fork/join as parallel branches)
    static cudaStream_t s2 = nullptr;
    static cudaEvent_t ev0 = nullptr, ev1 = nullptr;
    if (!s2) {
        cudaStreamCreateWithFlags(&s2, cudaStreamNonBlocking);
        cudaEventCreateWithFlags(&ev0, cudaEventDisableTiming);
        cudaEventCreateWithFlags(&ev1, cudaEventDisableTiming);
    }

    // fork: CSR build on s2, concurrent with FB/SAGE GEMMs on the main stream
    cudaEventRecord(ev0, 0);
    cudaStreamWaitEvent(s2, ev0, 0);
    k_zero_cnt<<<(n + 255) / 256, 256, 0, s2>>>(n);
    k_hist<<<(e + 255) / 256, 256, 0, s2>>>(ei, e, n);
    int nb = (n + 1023) / 1024;
    k_scan1<<<nb, 1024, 0, s2>>>(n);
    k_scan2<<<1, 256, 0, s2>>>(nb);
    k_scan3<<<(n + 255) / 256, 256, 0, s2>>>(n, e);
    k_fill<<<(e + 255) / 256, 256, 0, s2>>>(ei, e, n);
    cudaEventRecord(ev1, s2);

    int rowTiles = (n + 63) / 64;
    { dim3 g(2, rowTiles); k_fb1<<<g, 256>>>(x, fb_w1, n); }
    { dim3 g(3, rowTiles); k_fb2<<<g, 256>>>(x, fb_w2, n); }
    { dim3 g(4, rowTiles); k_dual<<<g, 256>>>(sage_wl, sage_wr, n); }

    // join: gathers need the CSR
    cudaStreamWaitEvent(0, ev1, 0);
    k_sage_fin<<<(n + 7) / 8, 256>>>(sage_bl, n);
    { dim3 g(1, rowTiles); k_gat_h<<<g, 256>>>(gat_w, att_s, att_d, n); }
    k_gat_agg<<<(n + 7) / 8, 256>>>(gat_b, cheb_w, cheb_b, out, n);
}

// round 5
// speedup vs baseline: 1.1971x; 1.1971x over previous
#include <cuda_runtime.h>
#include <cstdint>
#include <cstddef>

#define NN   100000
#define EE   1600000
#define DIN  165
#define DMID 82
#define DH   128
#define DG   64

// ---------------- scratch (static device globals) ---------------------------
__device__ float g_t  [NN * DMID];   // relu(x@W1)
__device__ float g_y1 [NN * DIN];    // boosted features
__device__ float g_zl [NN * DH];     // y1 @ sage_wl
__device__ float g_zr [NN * DH];     // y1 @ sage_wr
__device__ float g_x2 [NN * DH];     // SAGE output
__device__ float g_h  [NN * DG];     // GAT projected features
__device__ float g_as [NN];
__device__ float g_ad [NN];
__device__ int   g_cnt [NN];
__device__ int   g_rowptr[NN + 1];
__device__ int   g_cursor[NN];
__device__ int   g_bsum[256];
__device__ int   g_col [EE];

// ---------------- warp reduce helpers ---------------------------------------
__device__ __forceinline__ float wredmax(float v) {
    #pragma unroll
    for (int o = 16; o; o >>= 1) v = fmaxf(v, __shfl_xor_sync(0xffffffffu, v, o));
    return v;
}
__device__ __forceinline__ float wredsum(float v) {
    #pragma unroll
    for (int o = 16; o; o >>= 1) v += __shfl_xor_sync(0xffffffffu, v, o);
    return v;
}

// ---------------- CSR build --------------------------------------------------
__global__ void k_zero_cnt(int n) {
    int i = blockIdx.x * blockDim.x + threadIdx.x;
    if (i < n) g_cnt[i] = 0;
}

__global__ void k_hist(const int* __restrict__ ei, int e, int n) {
    int i = blockIdx.x * blockDim.x + threadIdx.x;
    if (i < e) {
        int d = ei[e + i];
        if ((unsigned)d < (unsigned)n) atomicAdd(&g_cnt[d], 1);
    }
}

__global__ void k_scan1(int n) {
    __shared__ int sh[1024];
    int t = threadIdx.x;
    int i = blockIdx.x * 1024 + t;
    int v = (i < n) ? g_cnt[i] : 0;
    sh[t] = v;
    __syncthreads();
    #pragma unroll
    for (int off = 1; off < 1024; off <<= 1) {
        int x = (t >= off) ? sh[t - off] : 0;
        __syncthreads();
        sh[t] += x;
        __syncthreads();
    }
    int incl = sh[t];
    if (i < n) g_rowptr[i] = incl - v;
    if (t == 1023) g_bsum[blockIdx.x] = incl;
}

__global__ void k_scan2(int nb) {
    __shared__ int sh[256];
    int t = threadIdx.x;
    int v = (t < nb) ? g_bsum[t] : 0;
    sh[t] = v;
    __syncthreads();
    #pragma unroll
    for (int off = 1; off < 256; off <<= 1) {
        int x = (t >= off) ? sh[t - off] : 0;
        __syncthreads();
        sh[t] += x;
        __syncthreads();
    }
    if (t < nb) g_bsum[t] = sh[t] - v;   // exclusive
}

__global__ void k_scan3(int n, int e) {
    int i = blockIdx.x * blockDim.x + threadIdx.x;
    if (i < n) {
        int v = g_rowptr[i] + g_bsum[i >> 10];
        g_rowptr[i] = v;
        g_cursor[i] = v;
    }
    if (i == 0) g_rowptr[n] = e;
}

__global__ void k_fill(const int* __restrict__ ei, int e, int n) {
    int i = blockIdx.x * blockDim.x + threadIdx.x;
    if (i < e) {
        int d = ei[e + i];
        int s = ei[i];
        if ((unsigned)d < (unsigned)n && (unsigned)s < (unsigned)n) {
            int pos = atomicAdd(&g_cursor[d], 1);
            g_col[pos] = s;
        }
    }
}

// ---------------- tiled SGEMM core (64x64 tile, 4x4 microtile, 256 thr) -----
template<int K, int M>
__device__ __forceinline__ void gemm_tile(
    const float* __restrict__ A, const float* __restrict__ W,
    int n, int rowBase, int colBase, int tid,
    float (*sA)[33], float (*sW)[64], float (&acc)[4][4])
{
    const int tx = tid & 15, ty = tid >> 4;
    for (int k0 = 0; k0 < K; k0 += 32) {
        #pragma unroll
        for (int i = 0; i < 8; i++) {
            int idx = tid + i * 256;
            int r = idx >> 5, kk = idx & 31;
            int row = rowBase + r, k = k0 + kk;
            sA[r][kk] = (row < n && k < K) ? A[(size_t)row * K + k] : 0.0f;
        }
        #pragma unroll
        for (int i = 0; i < 8; i++) {
            int idx = tid + i * 256;
            int kk = idx >> 6, c = idx & 63;
            int k = k0 + kk, col = colBase + c;
            sW[kk][c] = (k < K && col < M) ? W[(size_t)k * M + col] : 0.0f;
        }
        __syncthreads();
        #pragma unroll
        for (int kk = 0; kk < 32; kk++) {
            float4 b = *(const float4*)&sW[kk][tx * 4];
            float a0 = sA[ty * 4 + 0][kk];
            float a1 = sA[ty * 4 + 1][kk];
            float a2 = sA[ty * 4 + 2][kk];
            float a3 = sA[ty * 4 + 3][kk];
            acc[0][0] += a0 * b.x; acc[0][1] += a0 * b.y; acc[0][2] += a0 * b.z; acc[0][3] += a0 * b.w;
            acc[1][0] += a1 * b.x; acc[1][1] += a1 * b.y; acc[1][2] += a1 * b.z; acc[1][3] += a1 * b.w;
            acc[2][0] += a2 * b.x; acc[2][1] += a2 * b.y; acc[2][2] += a2 * b.z; acc[2][3] += a2 * b.w;
            acc[3][0] += a3 * b.x; acc[3][1] += a3 * b.y; acc[3][2] += a3 * b.z; acc[3][3] += a3 * b.w;
        }
        __syncthreads();
    }
}

// FB stage 1: g_t = relu(x @ fb_w1)
__global__ __launch_bounds__(256) void k_fb1(const float* __restrict__ x,
                                             const float* __restrict__ w1, int n)
{
    __shared__ float sA[64][33];
    __shared__ float sW[32][64];
    float acc[4][4] = {};
    int tid = threadIdx.x;
    int rowBase = blockIdx.y * 64, colBase = blockIdx.x * 64;
    gemm_tile<DIN, DMID>(x, w1, n, rowBase, colBase, tid, sA, sW, acc);
    int tx = tid & 15, ty = tid >> 4;
    #pragma unroll
    for (int i = 0; i < 4; i++) {
        int r = rowBase + ty * 4 + i;
        if (r >= n) continue;
        #pragma unroll
        for (int j = 0; j < 4; j++) {
            int c = colBase + tx * 4 + j;
            if (c < DMID) g_t[(size_t)r * DMID + c] = fmaxf(acc[i][j], 0.0f);
        }
    }
}

// FB stage 2: g_y1 = x * sigmoid(2 * (g_t @ fb_w2))
__global__ __launch_bounds__(256) void k_fb2(const float* __restrict__ x,
                                             const float* __restrict__ w2, int n)
{
    __shared__ float sA[64][33];
    __shared__ float sW[32][64];
    float acc[4][4] = {};
    int tid = threadIdx.x;
    int rowBase = blockIdx.y * 64, colBase = blockIdx.x * 64;
    gemm_tile<DMID, DIN>(g_t, w2, n, rowBase, colBase, tid, sA, sW, acc);
    int tx = tid & 15, ty = tid >> 4;
    #pragma unroll
    for (int i = 0; i < 4; i++) {
        int r = rowBase + ty * 4 + i;
        if (r >= n) continue;
        #pragma unroll
        for (int j = 0; j < 4; j++) {
            int c = colBase + tx * 4 + j;
            if (c < DIN) {
                float sig = 1.0f / (1.0f + __expf(-2.0f * acc[i][j]));
                g_y1[(size_t)r * DIN + c] = x[(size_t)r * DIN + c] * sig;
            }
        }
    }
}

// SAGE dual GEMM: zl = y1 @ wl, zr = y1 @ wr  (4 col tiles: 0,1->wl; 2,3->wr)
__global__ __launch_bounds__(256) void k_dual(const float* __restrict__ wl,
                                              const float* __restrict__ wr, int n)
{
    __shared__ float sA[64][33];
    __shared__ float sW[32][64];
    float acc[4][4] = {};
    int tid = threadIdx.x;
    int bx = blockIdx.x;
    const float* W   = (bx < 2) ? wl : wr;
    float*       dst = (bx < 2) ? g_zl : g_zr;
    int rowBase = blockIdx.y * 64, colBase = (bx & 1) * 64;
    gemm_tile<DIN, DH>(g_y1, W, n, rowBase, colBase, tid, sA, sW, acc);
    int tx = tid & 15, ty = tid >> 4;
    #pragma unroll
    for (int i = 0; i < 4; i++) {
        int r = rowBase + ty * 4 + i;
        if (r >= n) continue;
        #pragma unroll
        for (int j = 0; j < 4; j++) {
            int c = colBase + tx * 4 + j;
            dst[(size_t)r * DH + c] = acc[i][j];
        }
    }
}

// SAGE finalize: x2 = relu(mean_gather(zl) + zr + bl)   (warp per node)
__global__ __launch_bounds__(256) void k_sage_fin(const float* __restrict__ bl, int n)
{
    int w = (blockIdx.x * blockDim.x + threadIdx.x) >> 5;
    int lane = threadIdx.x & 31;
    if (w >= n) return;
    int beg = g_rowptr[w], end = g_rowptr[w + 1];
    float4 acc = make_float4(0.f, 0.f, 0.f, 0.f);
    int e = beg;
    for (; e + 2 <= end; e += 2) {
        const float4* p0 = (const float4*)(g_zl + (size_t)g_col[e]     * DH);
        const float4* p1 = (const float4*)(g_zl + (size_t)g_col[e + 1] * DH);
        float4 a = p0[lane], b = p1[lane];
        acc.x += a.x + b.x; acc.y += a.y + b.y;
        acc.z += a.z + b.z; acc.w += a.w + b.w;
    }
    if (e < end) {
        const float4* p0 = (const float4*)(g_zl + (size_t)g_col[e] * DH);
        float4 a = p0[lane];
        acc.x += a.x; acc.y += a.y; acc.z += a.z; acc.w += a.w;
    }
    float inv = 1.0f / fmaxf((float)(end - beg), 1.0f);
    const float4* zr  = (const float4*)(g_zr + (size_t)w * DH);
    const float4* bl4 = (const float4*)bl;
    float4 z = zr[lane], b4 = bl4[lane];
    float4 o;
    o.x = fmaxf(acc.x * inv + z.x + b4.x, 0.0f);
    o.y = fmaxf(acc.y * inv + z.y + b4.y, 0.0f);
    o.z = fmaxf(acc.z * inv + z.z + b4.z, 0.0f);
    o.w = fmaxf(acc.w * inv + z.w + b4.w, 0.0f);
    ((float4*)(g_x2 + (size_t)w * DH))[lane] = o;
}

// GAT projection + attention logits fused: g_h = x2 @ gat_w; as/ad per row.
__global__ __launch_bounds__(256) void k_gat_h(const float* __restrict__ gw,
                                               const float* __restrict__ att_s,
                                               const float* __restrict__ att_d, int n)
{
    __shared__ float sA[64][33];
    __shared__ float sW[32][64];
    float acc[4][4] = {};
    int tid = threadIdx.x;
    int rowBase = blockIdx.y * 64;
    gemm_tile<DH, DG>(g_x2, gw, n, rowBase, 0, tid, sA, sW, acc);
    int tx = tid & 15, ty = tid >> 4;
    #pragma unroll
    for (int i = 0; i < 4; i++) {
        int r = rowBase + ty * 4 + i;
        float ps = 0.0f, pd = 0.0f;
        #pragma unroll
        for (int j = 0; j < 4; j++) {
            int c = tx * 4 + j;
            if (r < n) g_h[(size_t)r * DG + c] = acc[i][j];
            ps += acc[i][j] * att_s[c];
            pd += acc[i][j] * att_d[c];
        }
        // reduce across the 16 tx lanes of this half-warp
        #pragma unroll
        for (int o = 8; o; o >>= 1) {
            ps += __shfl_xor_sync(0xffffffffu, ps, o);
            pd += __shfl_xor_sync(0xffffffffu, pd, o);
        }
        if (tx == 0 && r < n) { g_as[r] = ps; g_ad[r] = pd; }
    }
}

// GAT softmax-aggregate + bias + relu + Cheb(64->1) + sigmoid, fully fused.
__global__ __launch_bounds__(256) void k_gat_agg(const float* __restrict__ gat_b,
                                                 const float* __restrict__ cheb_w,
                                                 const float* __restrict__ cheb_b,
                                                 float* __restrict__ out, int n)
{
    int w = (blockIdx.x * blockDim.x + threadIdx.x) >> 5;
    int lane = threadIdx.x & 31;
    if (w >= n) return;
    int beg = g_rowptr[w], end = g_rowptr[w + 1];
    float ad_i = g_ad[w];
    float es = g_as[w] + ad_i;
    es = es > 0.0f ? es : 0.2f * es;            // self-loop leaky relu
    float m = es;
    for (int base = beg; base < end; base += 32) {
        int j = base + lane;
        float e = -1e30f;
        if (j < end) {
            int s = g_col[j];
            float t = g_as[s] + ad_i;
            e = t > 0.0f ? t : 0.2f * t;
        }
        m = fmaxf(m, e);
    }
    m = wredmax(m);
    float sl = 0.0f, a0 = 0.0f, a1 = 0.0f;
    for (int base = beg; base < end; base += 32) {
        int j = base + lane;
        int s = 0;
        float wgt = 0.0f;
        if (j < end) {
            s = g_col[j];
            float t = g_as[s] + ad_i;
            t = t > 0.0f ? t : 0.2f * t;
            wgt = __expf(t - m);
        }
        sl += wgt;
        int cnt = min(32, end - base);
        for (int jj = 0; jj < cnt; jj++) {
            float wj = __shfl_sync(0xffffffffu, wgt, jj);
            int   sj = __shfl_sync(0xffffffffu, s, jj);
            float2 hv = ((const float2*)(g_h + (size_t)sj * DG))[lane];
            a0 += wj * hv.x;
            a1 += wj * hv.y;
        }
    }
    float ws = __expf(es - m);
    float stot = wredsum(sl) + ws;
    float2 hi = ((const float2*)(g_h + (size_t)w * DG))[lane];
    a0 += ws * hi.x;
    a1 += ws * hi.y;
    float r = 1.0f / (stot + 1e-16f);
    float x0 = fmaxf(a0 * r + gat_b[2 * lane],     0.0f);
    float x1 = fmaxf(a1 * r + gat_b[2 * lane + 1], 0.0f);
    float part = x0 * cheb_w[2 * lane] + x1 * cheb_w[2 * lane + 1];
    part = wredsum(part);
    if (lane == 0) out[w] = 1.0f / (1.0f + __expf(-(part + cheb_b[0])));
}

// ---------------- launch -----------------------------------------------------
extern "C" void kernel_launch(void* const* d_in, const int* in_sizes, int n_in,
                              void* d_out, int out_size)
{
    const float* x       = (const float*)d_in[0];
    const int*   ei      = (const int*)d_in[1];       // int32
    const float* fb_w1   = (const float*)d_in[2];
    const float* fb_w2   = (const float*)d_in[3];
    const float* sage_wl = (const float*)d_in[4];
    const float* sage_bl = (const float*)d_in[5];
    const float* sage_wr = (const float*)d_in[6];
    const float* gat_w   = (const float*)d_in[7];
    const float* att_s   = (const float*)d_in[8];
    const float* att_d   = (const float*)d_in[9];
    const float* gat_b   = (const float*)d_in[10];
    const float* cheb_w  = (const float*)d_in[11];
    const float* cheb_b  = (const float*)d_in[12];
    float*       out     = (float*)d_out;

    int n = in_sizes[0] / DIN;
    int e = in_sizes[1] / 2;

    // CSR build (by dst) — serialized on the main stream (fork regressed in R3)
    k_zero_cnt<<<(n + 255) / 256, 256>>>(n);
    k_hist<<<(e + 255) / 256, 256>>>(ei, e, n);
    int nb = (n + 1023) / 1024;
    k_scan1<<<nb, 1024>>>(n);
    k_scan2<<<1, 256>>>(nb);
    k_scan3<<<(n + 255) / 256, 256>>>(n, e);
    k_fill<<<(e + 255) / 256, 256>>>(ei, e, n);

    int rowTiles = (n + 63) / 64;
    // FeatureBooster
    { dim3 g(2, rowTiles); k_fb1<<<g, 256>>>(x, fb_w1, n); }
    { dim3 g(3, rowTiles); k_fb2<<<g, 256>>>(x, fb_w2, n); }
    // SAGE (projected space)
    { dim3 g(4, rowTiles); k_dual<<<g, 256>>>(sage_wl, sage_wr, n); }
    k_sage_fin<<<(n + 7) / 8, 256>>>(sage_bl, n);
    // GAT
    { dim3 g(1, rowTiles); k_gat_h<<<g, 256>>>(gat_w, att_s, att_d, n); }
    k_gat_agg<<<(n + 7) / 8, 256>>>(gat_b, cheb_w, cheb_b, out, n);
}